// round 1
// baseline (speedup 1.0000x reference)
#include <cuda_runtime.h>
#include <cstdint>
#include <math.h>

#define T_     256
#define B_     32
#define VOCAB_ 32000
#define EMB_   512
#define HID_   1024
#define G_     4096   // 4*HID
#define TB_    8192   // T_*B_

// ---------------- scratch (device globals; no allocations allowed) ----------
__device__ float g_X0[TB_ * EMB_];            // 16.7 MB embedding output
__device__ float g_HA[TB_ * HID_];            // 33.5 MB layer output ping
__device__ float g_HB[TB_ * HID_];            // 33.5 MB layer output pong
__device__ float g_Xg[(size_t)TB_ * G_];      // 134 MB precomputed x-gates
__device__ float g_h[2 * B_ * HID_];          // double-buffered h state
__device__ float g_c[B_ * HID_];              // c state

// ---------------- helpers ---------------------------------------------------
__device__ __forceinline__ float f2tf32(float x) {
    uint32_t u;
    asm("cvt.rna.tf32.f32 %0, %1;" : "=r"(u) : "f"(x));
    return __uint_as_float(u);
}

__device__ __forceinline__ void mma_tf32(float* d, const uint32_t* a, const uint32_t* b) {
    asm volatile(
        "mma.sync.aligned.m16n8k8.row.col.f32.tf32.tf32.f32 "
        "{%0,%1,%2,%3}, {%4,%5,%6,%7}, {%8,%9}, {%0,%1,%2,%3};\n"
        : "+f"(d[0]), "+f"(d[1]), "+f"(d[2]), "+f"(d[3])
        : "r"(a[0]), "r"(a[1]), "r"(a[2]), "r"(a[3]), "r"(b[0]), "r"(b[1]));
}

__device__ __forceinline__ float sigm(float x) { return 1.f / (1.f + expf(-x)); }

// ---------------- embedding gather ------------------------------------------
__global__ void gather_kernel(const int* __restrict__ data,
                              const float* __restrict__ emb,
                              float* __restrict__ X0) {
    int tb = blockIdx.x;
    int idx = data[tb];
    const float4* src = reinterpret_cast<const float4*>(emb + (size_t)idx * EMB_);
    float4* dst = reinterpret_cast<float4*>(X0 + (size_t)tb * EMB_);
    dst[threadIdx.x] = src[threadIdx.x];   // 128 threads * 4 floats = 512
}

// ---------------- state zero ------------------------------------------------
__global__ void zero_state(float* __restrict__ h, float* __restrict__ c) {
    int i = blockIdx.x * blockDim.x + threadIdx.x;
    if (i < 2 * B_ * HID_) h[i] = 0.f;
    if (i < B_ * HID_)     c[i] = 0.f;
}

// ---------------- generic TF32 GEMM: C = A@B + bias -------------------------
// A [M, lda] row-major, B [K, ldb] row-major, C [M, ldc].
// grid (N/128, M/128), 256 threads. M,N % 128 == 0, K % 16 == 0 (guaranteed).
__global__ __launch_bounds__(256) void gemm_tf32_bias(
    const float* __restrict__ A, int lda,
    const float* __restrict__ Bm, int ldb,
    const float* __restrict__ bias,
    float* __restrict__ C, int ldc, int K)
{
    __shared__ float As[16][132];   // [k][m]
    __shared__ float Bs[16][136];   // [k][n]

    const int n0 = blockIdx.x * 128;
    const int m0 = blockIdx.y * 128;
    const int tid = threadIdx.x;
    const int lane = tid & 31, warp = tid >> 5;
    const int wm = (warp & 3) * 32;    // 4 warps along M
    const int wn = (warp >> 2) * 64;   // 2 warps along N
    const int g = lane >> 2, tig = lane & 3;

    float acc[2][8][4];
#pragma unroll
    for (int i = 0; i < 2; i++)
#pragma unroll
        for (int j = 0; j < 8; j++)
#pragma unroll
            for (int r = 0; r < 4; r++) acc[i][j][r] = 0.f;

    float4 ra[2], rb[2];

    auto ldglobal = [&](int k0) {
#pragma unroll
        for (int i = 0; i < 2; i++) {
            int c = tid + i * 256;
            int r = c >> 2, kq = (c & 3) << 2;
            ra[i] = *reinterpret_cast<const float4*>(A + (size_t)(m0 + r) * lda + (k0 + kq));
            int k = c >> 5, nq = (c & 31) << 2;
            rb[i] = *reinterpret_cast<const float4*>(Bm + (size_t)(k0 + k) * ldb + (n0 + nq));
        }
    };
    auto st_smem = [&]() {
#pragma unroll
        for (int i = 0; i < 2; i++) {
            int c = tid + i * 256;
            int r = c >> 2, kq = (c & 3) << 2;
            As[kq + 0][r] = f2tf32(ra[i].x);
            As[kq + 1][r] = f2tf32(ra[i].y);
            As[kq + 2][r] = f2tf32(ra[i].z);
            As[kq + 3][r] = f2tf32(ra[i].w);
            int k = c >> 5, nq = (c & 31) << 2;
            float4 t;
            t.x = f2tf32(rb[i].x); t.y = f2tf32(rb[i].y);
            t.z = f2tf32(rb[i].z); t.w = f2tf32(rb[i].w);
            *reinterpret_cast<float4*>(&Bs[k][nq]) = t;
        }
    };
    auto compute = [&]() {
#pragma unroll
        for (int ks = 0; ks < 16; ks += 8) {
            uint32_t af[2][4];
#pragma unroll
            for (int mt = 0; mt < 2; mt++) {
                int mb = wm + mt * 16;
                af[mt][0] = __float_as_uint(As[ks + tig][mb + g]);
                af[mt][1] = __float_as_uint(As[ks + tig][mb + g + 8]);
                af[mt][2] = __float_as_uint(As[ks + tig + 4][mb + g]);
                af[mt][3] = __float_as_uint(As[ks + tig + 4][mb + g + 8]);
            }
#pragma unroll
            for (int nt = 0; nt < 8; nt++) {
                uint32_t bf[2];
                int nb = wn + nt * 8;
                bf[0] = __float_as_uint(Bs[ks + tig][nb + g]);
                bf[1] = __float_as_uint(Bs[ks + tig + 4][nb + g]);
                mma_tf32(acc[0][nt], af[0], bf);
                mma_tf32(acc[1][nt], af[1], bf);
            }
        }
    };

    ldglobal(0); st_smem(); __syncthreads();
    const int nk = K >> 4;
    for (int kb = 0; kb < nk; kb++) {
        bool more = (kb + 1 < nk);
        if (more) ldglobal((kb + 1) << 4);
        compute();
        __syncthreads();
        if (more) { st_smem(); __syncthreads(); }
    }

#pragma unroll
    for (int mt = 0; mt < 2; mt++) {
        int m = m0 + wm + mt * 16 + g;
#pragma unroll
        for (int nt = 0; nt < 8; nt++) {
            int n = n0 + wn + nt * 8 + 2 * tig;
            float bx = bias[n], by = bias[n + 1];
            float2 v0 = make_float2(acc[mt][nt][0] + bx, acc[mt][nt][1] + by);
            float2 v1 = make_float2(acc[mt][nt][2] + bx, acc[mt][nt][3] + by);
            *reinterpret_cast<float2*>(C + (size_t)m * ldc + n) = v0;
            *reinterpret_cast<float2*>(C + (size_t)(m + 8) * ldc + n) = v1;
        }
    }
}

// ---------------- LSTM recurrence step --------------------------------------
// gates[32, {i,g,f,o} x 16 units] = Xg[t] + h_{t-1} @ Wh, then pointwise.
// grid 64 blocks (16 units each), 128 threads (4 warps).
// warp = 2*kh + uw_sel: kh picks K half (0:[0,512), 1:[512,1024)),
// uw_sel picks unit subgroup of 8. Pointwise fused in epilogue (registers only).
__global__ __launch_bounds__(128) void lstm_step(
    int t,
    const float* __restrict__ Xg,
    const float* __restrict__ Wh,      // rows Din..Din+H of W: [HID_][G_]
    float* __restrict__ hbuf,          // [2][B_*HID_]
    float* __restrict__ cst,           // [B_*HID_]
    float* __restrict__ Hout)          // [TB_*HID_]
{
    const float* hin = hbuf + (t & 1) * (B_ * HID_);
    float* hnext = hbuf + ((t + 1) & 1) * (B_ * HID_);
    const int u0 = blockIdx.x * 16;

    __shared__ float Hs[2][32][36];        // [khalf][k][m]
    __shared__ float Ws[2][32][72];        // [khalf][k][s*16 + unitLocal]
    __shared__ float accbuf[32][32];       // [reg(= (w&1)*?? no: see below)][lane]

    const int tid = threadIdx.x;
    const int lane = tid & 31, warp = tid >> 5;
    const int kh = warp >> 1;          // K half this warp computes
    const int uw = (warp & 1) * 8;     // unit subgroup offset
    const int g = lane >> 2, tig = lane & 3;
    const int grp = tid >> 6;          // 64-thread load group -> K half
    const int gt = tid & 63;

    float acc[2][4][4];
#pragma unroll
    for (int i = 0; i < 2; i++)
#pragma unroll
        for (int s = 0; s < 4; s++)
#pragma unroll
            for (int r = 0; r < 4; r++) acc[i][s][r] = 0.f;

    float4 rh[4], rw[8];

    auto ldg = [&](int kb) {
        int kbase = grp * 512 + kb * 32;
#pragma unroll
        for (int i = 0; i < 4; i++) {           // Hs: 32m x 32k
            int c = gt + i * 64;                // 0..255 float4s
            int m = c >> 3, kq = (c & 7) << 2;
            rh[i] = *reinterpret_cast<const float4*>(hin + (size_t)m * HID_ + kbase + kq);
        }
#pragma unroll
        for (int i = 0; i < 8; i++) {           // Ws: 32k x 64 cols
            int c = gt + i * 64;                // 0..511 float4s
            int k = c >> 4, q = (c & 15) << 2;  // q in {0..60}
            int s = q >> 4, j = q & 15;         // gate, unit offset
            rw[i] = *reinterpret_cast<const float4*>(
                Wh + (size_t)(kbase + k) * G_ + s * HID_ + u0 + j);
        }
    };
    auto sts = [&]() {
#pragma unroll
        for (int i = 0; i < 4; i++) {
            int c = gt + i * 64;
            int m = c >> 3, kq = (c & 7) << 2;
            Hs[grp][kq + 0][m] = f2tf32(rh[i].x);
            Hs[grp][kq + 1][m] = f2tf32(rh[i].y);
            Hs[grp][kq + 2][m] = f2tf32(rh[i].z);
            Hs[grp][kq + 3][m] = f2tf32(rh[i].w);
        }
#pragma unroll
        for (int i = 0; i < 8; i++) {
            int c = gt + i * 64;
            int k = c >> 4, q = (c & 15) << 2;
            float4 tv;
            tv.x = f2tf32(rw[i].x); tv.y = f2tf32(rw[i].y);
            tv.z = f2tf32(rw[i].z); tv.w = f2tf32(rw[i].w);
            *reinterpret_cast<float4*>(&Ws[grp][k][q]) = tv;
        }
    };
    auto compute = [&]() {
#pragma unroll
        for (int ks = 0; ks < 32; ks += 8) {
            uint32_t af[2][4];
#pragma unroll
            for (int mt = 0; mt < 2; mt++) {
                int mb = mt * 16;
                af[mt][0] = __float_as_uint(Hs[kh][ks + tig][mb + g]);
                af[mt][1] = __float_as_uint(Hs[kh][ks + tig][mb + g + 8]);
                af[mt][2] = __float_as_uint(Hs[kh][ks + tig + 4][mb + g]);
                af[mt][3] = __float_as_uint(Hs[kh][ks + tig + 4][mb + g + 8]);
            }
#pragma unroll
            for (int s = 0; s < 4; s++) {
                uint32_t bf[2];
                int nb = s * 16 + uw + g;
                bf[0] = __float_as_uint(Ws[kh][ks + tig][nb]);
                bf[1] = __float_as_uint(Ws[kh][ks + tig + 4][nb]);
                mma_tf32(acc[0][s], af[0], bf);
                mma_tf32(acc[1][s], af[1], bf);
            }
        }
    };

    ldg(0); sts(); __syncthreads();
    for (int kb = 0; kb < 16; kb++) {
        bool more = (kb + 1 < 16);
        if (more) ldg(kb + 1);
        compute();
        __syncthreads();
        if (more) { sts(); __syncthreads(); }
    }

    // combine K halves: kh==1 warps publish, kh==0 warps reduce + pointwise.
    // accbuf layout: [ (w&1)*16 ... ] -> [reg][lane] per unit-subgroup, split
    // the 32 regs as idx = (warp&1)*0 + ... use [unitgrp sel via reg block]:
    if (kh == 1) {
#pragma unroll
        for (int mt = 0; mt < 2; mt++)
#pragma unroll
            for (int s = 0; s < 4; s++)
#pragma unroll
                for (int r = 0; r < 4; r++) {
                    int idx = mt * 16 + s * 4 + r;  // 0..31
                    // two unit subgroups share accbuf: interleave on idx parity-free:
                    // subgroup 0 uses rows [0..31] lanes, subgroup 1 also rows [0..31]
                    // -> disambiguate via column halves: lane + 0 vs nothing; instead
                    // use separate row blocks: (warp&1) selects top/bottom 16 rows twice.
                    accbuf[idx][lane] = (warp & 1) ? accbuf[idx][lane] : acc[mt][s][r];
                    if (warp & 1) accbuf[idx][lane] = acc[mt][s][r];
                }
    }
    __syncthreads();
    // NOTE: the above would collide between the two kh==1 warps; they write the
    // same [idx][lane] cells. Avoided by giving each unit-subgroup its own half:
    // (this comment documents the fix below — recompute properly)
    __syncthreads();
    // Proper publish: redo with disjoint regions (idx offset by subgroup*32 is
    // impossible in 32 rows, so use lane columns shifted by subgroup in a 2nd pass)
    if (kh == 1) {
        // nothing further; see corrected scheme below
    }

    // ---- corrected combine: each kh==1 warp has a unique (warp&1); store into
    //      a disjoint 16-float chunk pair by reusing Ws as scratch -------------
    float* scratch = &Ws[0][0][0];   // 2*32*72 = 4608 floats, plenty
    if (kh == 1) {
        float* dst = scratch + (warp & 1) * 1024 + lane * 32;
#pragma unroll
        for (int mt = 0; mt < 2; mt++)
#pragma unroll
            for (int s = 0; s < 4; s++)
#pragma unroll
                for (int r = 0; r < 4; r++)
                    dst[mt * 16 + s * 4 + r] = acc[mt][s][r];
    }
    __syncthreads();
    if (kh == 0) {
        const float* src = scratch + (warp & 1) * 1024 + lane * 32;
#pragma unroll
        for (int mt = 0; mt < 2; mt++) {
#pragma unroll
            for (int dm = 0; dm < 2; dm++) {
                int m = mt * 16 + g + dm * 8;
#pragma unroll
                for (int du = 0; du < 2; du++) {
                    int u = u0 + uw + 2 * tig + du;
                    int r = dm * 2 + du;
                    float iv = acc[mt][0][r] + src[mt * 16 + 0 * 4 + r];
                    float gv = acc[mt][1][r] + src[mt * 16 + 1 * 4 + r];
                    float fv = acc[mt][2][r] + src[mt * 16 + 2 * 4 + r];
                    float ov = acc[mt][3][r] + src[mt * 16 + 3 * 4 + r];
                    size_t xb = ((size_t)(t * B_ + m)) * G_ + u;
                    iv += Xg[xb];
                    gv += Xg[xb + HID_];
                    fv += Xg[xb + 2 * HID_];
                    ov += Xg[xb + 3 * HID_];
                    int ci = m * HID_ + u;
                    float cc = cst[ci];
                    cc = sigm(fv + 1.f) * cc + sigm(iv) * tanhf(gv);
                    float hh = sigm(ov) * tanhf(cc);
                    cst[ci] = cc;
                    hnext[ci] = hh;
                    Hout[((size_t)(t * B_ + m)) * HID_ + u] = hh;
                }
            }
        }
    }
}

// ---------------- launch ----------------------------------------------------
extern "C" void kernel_launch(void* const* d_in, const int* in_sizes, int n_in,
                              void* d_out, int out_size) {
    const int*   data = (const int*)d_in[0];
    const float* emb  = (const float*)d_in[2];
    const float* W0   = (const float*)d_in[3];
    const float* b0   = (const float*)d_in[4];
    const float* W1   = (const float*)d_in[5];
    const float* b1   = (const float*)d_in[6];
    const float* W2   = (const float*)d_in[7];
    const float* b2   = (const float*)d_in[8];
    const float* Wd   = (const float*)d_in[9];
    const float* bd   = (const float*)d_in[10];
    float* out = (float*)d_out;
    (void)in_sizes; (void)n_in; (void)out_size;

    float *X0, *HA, *HB, *Xg, *h, *c;
    cudaGetSymbolAddress((void**)&X0, g_X0);
    cudaGetSymbolAddress((void**)&HA, g_HA);
    cudaGetSymbolAddress((void**)&HB, g_HB);
    cudaGetSymbolAddress((void**)&Xg, g_Xg);
    cudaGetSymbolAddress((void**)&h,  g_h);
    cudaGetSymbolAddress((void**)&c,  g_c);

    gather_kernel<<<TB_, 128>>>(data, emb, X0);

    const int zgrid = (2 * B_ * HID_ + 255) / 256;

    // layer 0: input X0 (Din=512) -> HA
    zero_state<<<zgrid, 256>>>(h, c);
    gemm_tf32_bias<<<dim3(G_ / 128, TB_ / 128), 256>>>(X0, EMB_, W0, G_, b0, Xg, G_, EMB_);
    for (int t = 0; t < T_; t++)
        lstm_step<<<64, 128>>>(t, Xg, W0 + (size_t)EMB_ * G_, h, c, HA);

    // layer 1: HA (Din=1024) -> HB
    zero_state<<<zgrid, 256>>>(h, c);
    gemm_tf32_bias<<<dim3(G_ / 128, TB_ / 128), 256>>>(HA, HID_, W1, G_, b1, Xg, G_, HID_);
    for (int t = 0; t < T_; t++)
        lstm_step<<<64, 128>>>(t, Xg, W1 + (size_t)HID_ * G_, h, c, HB);

    // layer 2: HB (Din=1024) -> HA
    zero_state<<<zgrid, 256>>>(h, c);
    gemm_tf32_bias<<<dim3(G_ / 128, TB_ / 128), 256>>>(HB, HID_, W2, G_, b2, Xg, G_, HID_);
    for (int t = 0; t < T_; t++)
        lstm_step<<<64, 128>>>(t, Xg, W2 + (size_t)HID_ * G_, h, c, HA);

    // projection: HA @ Wd + bd -> out [8192, 32000]
    gemm_tf32_bias<<<dim3(VOCAB_ / 128, TB_ / 128), 256>>>(HA, HID_, Wd, VOCAB_, bd,
                                                           out, VOCAB_, HID_);
}

// round 2
// speedup vs baseline: 2.0394x; 2.0394x over previous
#include <cuda_runtime.h>
#include <cstdint>
#include <math.h>

#define T_     256
#define B_     32
#define VOCAB_ 32000
#define EMB_   512
#define HID_   1024
#define G_     4096   // 4*HID
#define TB_    8192   // T_*B_
#define NBLK   128    // persistent blocks (1 per SM, <=148)
#define UPB    8      // hidden units per block (128*8 = 1024)
#define BH     (B_ * HID_)

// ---------------- scratch (device globals; no allocations allowed) ----------
__device__ float g_X0[TB_ * EMB_];
__device__ float g_HA[TB_ * HID_];
__device__ float g_HB[TB_ * HID_];
__device__ float g_Xg[(size_t)TB_ * G_];
__device__ float g_h[2 * BH];              // ping-pong h state
__device__ unsigned g_bar;                 // grid barrier counter

// ---------------- helpers ---------------------------------------------------
__device__ __forceinline__ float f2tf32(float x) {
    uint32_t u;
    asm("cvt.rna.tf32.f32 %0, %1;" : "=r"(u) : "f"(x));
    return __uint_as_float(u);
}

__device__ __forceinline__ void mma_tf32(float* d, const uint32_t* a, const uint32_t* b) {
    asm volatile(
        "mma.sync.aligned.m16n8k8.row.col.f32.tf32.tf32.f32 "
        "{%0,%1,%2,%3}, {%4,%5,%6,%7}, {%8,%9}, {%0,%1,%2,%3};\n"
        : "+f"(d[0]), "+f"(d[1]), "+f"(d[2]), "+f"(d[3])
        : "r"(a[0]), "r"(a[1]), "r"(a[2]), "r"(a[3]), "r"(b[0]), "r"(b[1]));
}

__device__ __forceinline__ float sigm(float x) { return 1.f / (1.f + expf(-x)); }

__device__ __forceinline__ unsigned ld_acq(const unsigned* p) {
    unsigned v;
    asm volatile("ld.acquire.gpu.u32 %0, [%1];" : "=r"(v) : "l"(p) : "memory");
    return v;
}

// Hs swizzle: addr(k, m) = k*32 + (m ^ fsw(k));  STS <=2-way, LDS conflict-free
__device__ __forceinline__ int fsw(int k) {
    return ((k & 3) << 3) ^ (((k >> 2) & 7) << 2);
}

// ---------------- embedding gather ------------------------------------------
__global__ void gather_kernel(const int* __restrict__ data,
                              const float* __restrict__ emb,
                              float* __restrict__ X0) {
    int tb = blockIdx.x;
    int idx = data[tb];
    const float4* src = reinterpret_cast<const float4*>(emb + (size_t)idx * EMB_);
    float4* dst = reinterpret_cast<float4*>(X0 + (size_t)tb * EMB_);
    dst[threadIdx.x] = src[threadIdx.x];
}

// ---------------- state zero + barrier reset --------------------------------
__global__ void zero_state(float* __restrict__ h, unsigned* __restrict__ bar) {
    int i = blockIdx.x * blockDim.x + threadIdx.x;
    if (i < 2 * BH) h[i] = 0.f;
    if (i == 0) *bar = 0u;
}

// ---------------- generic TF32 GEMM: C = A@B + bias (round-0, validated) ----
__global__ __launch_bounds__(256) void gemm_tf32_bias(
    const float* __restrict__ A, int lda,
    const float* __restrict__ Bm, int ldb,
    const float* __restrict__ bias,
    float* __restrict__ C, int ldc, int K)
{
    __shared__ float As[16][132];
    __shared__ float Bs[16][136];

    const int n0 = blockIdx.x * 128;
    const int m0 = blockIdx.y * 128;
    const int tid = threadIdx.x;
    const int lane = tid & 31, warp = tid >> 5;
    const int wm = (warp & 3) * 32;
    const int wn = (warp >> 2) * 64;
    const int g = lane >> 2, tig = lane & 3;

    float acc[2][8][4];
#pragma unroll
    for (int i = 0; i < 2; i++)
#pragma unroll
        for (int j = 0; j < 8; j++)
#pragma unroll
            for (int r = 0; r < 4; r++) acc[i][j][r] = 0.f;

    float4 ra[2], rb[2];

    auto ldglobal = [&](int k0) {
#pragma unroll
        for (int i = 0; i < 2; i++) {
            int c = tid + i * 256;
            int r = c >> 2, kq = (c & 3) << 2;
            ra[i] = *reinterpret_cast<const float4*>(A + (size_t)(m0 + r) * lda + (k0 + kq));
            int k = c >> 5, nq = (c & 31) << 2;
            rb[i] = *reinterpret_cast<const float4*>(Bm + (size_t)(k0 + k) * ldb + (n0 + nq));
        }
    };
    auto st_smem = [&]() {
#pragma unroll
        for (int i = 0; i < 2; i++) {
            int c = tid + i * 256;
            int r = c >> 2, kq = (c & 3) << 2;
            As[kq + 0][r] = f2tf32(ra[i].x);
            As[kq + 1][r] = f2tf32(ra[i].y);
            As[kq + 2][r] = f2tf32(ra[i].z);
            As[kq + 3][r] = f2tf32(ra[i].w);
            int k = c >> 5, nq = (c & 31) << 2;
            float4 t;
            t.x = f2tf32(rb[i].x); t.y = f2tf32(rb[i].y);
            t.z = f2tf32(rb[i].z); t.w = f2tf32(rb[i].w);
            *reinterpret_cast<float4*>(&Bs[k][nq]) = t;
        }
    };
    auto compute = [&]() {
#pragma unroll
        for (int ks = 0; ks < 16; ks += 8) {
            uint32_t af[2][4];
#pragma unroll
            for (int mt = 0; mt < 2; mt++) {
                int mb = wm + mt * 16;
                af[mt][0] = __float_as_uint(As[ks + tig][mb + g]);
                af[mt][1] = __float_as_uint(As[ks + tig][mb + g + 8]);
                af[mt][2] = __float_as_uint(As[ks + tig + 4][mb + g]);
                af[mt][3] = __float_as_uint(As[ks + tig + 4][mb + g + 8]);
            }
#pragma unroll
            for (int nt = 0; nt < 8; nt++) {
                uint32_t bf[2];
                int nb = wn + nt * 8;
                bf[0] = __float_as_uint(Bs[ks + tig][nb + g]);
                bf[1] = __float_as_uint(Bs[ks + tig + 4][nb + g]);
                mma_tf32(acc[0][nt], af[0], bf);
                mma_tf32(acc[1][nt], af[1], bf);
            }
        }
    };

    ldglobal(0); st_smem(); __syncthreads();
    const int nk = K >> 4;
    for (int kb = 0; kb < nk; kb++) {
        bool more = (kb + 1 < nk);
        if (more) ldglobal((kb + 1) << 4);
        compute();
        __syncthreads();
        if (more) { st_smem(); __syncthreads(); }
    }

#pragma unroll
    for (int mt = 0; mt < 2; mt++) {
        int m = m0 + wm + mt * 16 + g;
#pragma unroll
        for (int nt = 0; nt < 8; nt++) {
            int n = n0 + wn + nt * 8 + 2 * tig;
            float bx = bias[n], by = bias[n + 1];
            float2 v0 = make_float2(acc[mt][nt][0] + bx, acc[mt][nt][1] + by);
            float2 v1 = make_float2(acc[mt][nt][2] + bx, acc[mt][nt][3] + by);
            *reinterpret_cast<float2*>(C + (size_t)m * ldc + n) = v0;
            *reinterpret_cast<float2*>(C + (size_t)(m + 8) * ldc + n) = v1;
        }
    }
}

// ---------------- persistent LSTM layer -------------------------------------
// 128 blocks x 128 threads. Block owns UPB=8 units (32 gate columns).
// Wh slice resident in SMEM as pre-permuted mma B-fragments for all 256 steps.
// c state in registers. Grid barrier between steps.
//
// Dynamic SMEM layout:
//   Whs : float2[128 ko][4 nt][32 lane]          = 131072 B
//   Hs  : float [4 warp][64 k][32 m] (swizzled)  =  32768 B
//   scr : float [4 warp][32 ridx][32 lane]       =  16384 B
#define WHS_BYTES 131072
#define HS_BYTES  32768
#define SCR_BYTES 16384
#define SMEM_PERSIST (WHS_BYTES + HS_BYTES + SCR_BYTES)

__global__ __launch_bounds__(128, 1) void lstm_persist(
    const float* __restrict__ Xg,
    const float* __restrict__ Wh,      // [HID_][G_] (rows Din..Din+H of W)
    float* __restrict__ hbuf,          // [2][BH] (zeroed)
    float* __restrict__ Hout,          // [TB_][HID_]
    unsigned* __restrict__ bar)
{
    extern __shared__ char smx[];
    float2* Whs = reinterpret_cast<float2*>(smx);
    float*  Hs  = reinterpret_cast<float*>(smx + WHS_BYTES);
    float*  scr = reinterpret_cast<float*>(smx + WHS_BYTES + HS_BYTES);

    const int tid = threadIdx.x;
    const int lane = tid & 31, warp = tid >> 5;
    const int g = lane >> 2, tig = lane & 3;
    const int u0 = blockIdx.x * UPB;
    float* Hw = Hs + warp * 2048;   // this warp's 64x32 chunk buffer

    // ---- one-time: load Wh slice into fragment layout ----
    for (int ko = warp; ko < 128; ko += 4) {
#pragma unroll
        for (int nt = 0; nt < 4; nt++) {
            int col = nt * HID_ + u0 + g;
            float b0 = Wh[(size_t)(ko * 8 + tig) * G_ + col];
            float b1 = Wh[(size_t)(ko * 8 + tig + 4) * G_ + col];
            Whs[(ko * 4 + nt) * 32 + lane] = make_float2(f2tf32(b0), f2tf32(b1));
        }
    }
    __syncthreads();

    // c state in registers: thread owns pairs p = tid and p = tid+128
    float creg[2] = {0.f, 0.f};

    for (int t = 0; t < T_; t++) {
        const float* hin = hbuf + (t & 1) * BH;
        float* hnx = hbuf + ((t + 1) & 1) * BH;

        float acc[2][4][4];
#pragma unroll
        for (int mt = 0; mt < 2; mt++)
#pragma unroll
            for (int nt = 0; nt < 4; nt++)
#pragma unroll
                for (int r = 0; r < 4; r++) acc[mt][nt][r] = 0.f;

        float4 rr[16];
        const int kw = warp * 256;

        auto ldg_chunk = [&](int c) {
            int kb = kw + c * 64;
#pragma unroll
            for (int i = 0; i < 16; i++) {
                int idx = i * 32 + lane;
                int row = idx >> 4, kq = (idx & 15) << 2;
                rr[i] = *reinterpret_cast<const float4*>(hin + row * HID_ + kb + kq);
            }
        };
        auto sts_chunk = [&]() {
#pragma unroll
            for (int i = 0; i < 16; i++) {
                int idx = i * 32 + lane;
                int row = idx >> 4, kq = (idx & 15) << 2;
                float v[4] = {rr[i].x, rr[i].y, rr[i].z, rr[i].w};
#pragma unroll
                for (int j = 0; j < 4; j++) {
                    int k = kq + j;
                    Hw[(k << 5) + (row ^ fsw(k))] = f2tf32(v[j]);
                }
            }
        };
        auto compute_chunk = [&](int c) {
#pragma unroll
            for (int ks8 = 0; ks8 < 8; ks8++) {
                int ko = warp * 32 + c * 8 + ks8;   // global k/8
                uint32_t af[2][4];
#pragma unroll
                for (int mt = 0; mt < 2; mt++) {
                    int mb = mt * 16;
                    int kA = ks8 * 8 + tig;
                    int kB = kA + 4;
                    af[mt][0] = __float_as_uint(Hw[(kA << 5) + ((mb + g) ^ fsw(kA))]);
                    af[mt][1] = __float_as_uint(Hw[(kA << 5) + ((mb + g + 8) ^ fsw(kA))]);
                    af[mt][2] = __float_as_uint(Hw[(kB << 5) + ((mb + g) ^ fsw(kB))]);
                    af[mt][3] = __float_as_uint(Hw[(kB << 5) + ((mb + g + 8) ^ fsw(kB))]);
                }
#pragma unroll
                for (int nt = 0; nt < 4; nt++) {
                    float2 bb = Whs[(ko * 4 + nt) * 32 + lane];
                    uint32_t bf[2] = {__float_as_uint(bb.x), __float_as_uint(bb.y)};
                    mma_tf32(acc[0][nt], af[0], bf);
                    mma_tf32(acc[1][nt], af[1], bf);
                }
            }
        };

        ldg_chunk(0);
        sts_chunk();
        __syncwarp();
        for (int c = 0; c < 4; c++) {
            if (c < 3) ldg_chunk(c + 1);
            compute_chunk(c);
            __syncwarp();
            if (c < 3) { sts_chunk(); __syncwarp(); }
        }

        // ---- reduce K-partials across warps ----
        __syncthreads();
#pragma unroll
        for (int mt = 0; mt < 2; mt++)
#pragma unroll
            for (int nt = 0; nt < 4; nt++)
#pragma unroll
                for (int r = 0; r < 4; r++) {
                    int ridx = mt * 16 + nt * 4 + r;
                    scr[((warp * 32 + ridx) << 5) + lane] = acc[mt][nt][r];
                }
        __syncthreads();

        // ---- pointwise: 2 (batch,unit) pairs per thread ----
#pragma unroll
        for (int pp = 0; pp < 2; pp++) {
            int p = tid + pp * 128;       // p = m*8 + ul
            int m = p >> 3, ul = p & 7;
            int m16 = m & 15, mt = m >> 4;
            int gg = m16 & 7, hi = m16 >> 3;
            int ltig = ul >> 1, par = ul & 1;
            int r = hi * 2 + par;
            int ln = gg * 4 + ltig;

            float gv[4];
#pragma unroll
            for (int s = 0; s < 4; s++) {
                int ridx = mt * 16 + s * 4 + r;
                float v = scr[((0 * 32 + ridx) << 5) + ln]
                        + scr[((1 * 32 + ridx) << 5) + ln]
                        + scr[((2 * 32 + ridx) << 5) + ln]
                        + scr[((3 * 32 + ridx) << 5) + ln];
                gv[s] = v + Xg[((size_t)(t * B_ + m)) * G_ + s * HID_ + u0 + ul];
            }
            float cc = creg[pp];
            cc = sigm(gv[2] + 1.f) * cc + sigm(gv[0]) * tanhf(gv[1]);
            float hh = sigm(gv[3]) * tanhf(cc);
            creg[pp] = cc;
            hnx[m * HID_ + u0 + ul] = hh;
            Hout[((size_t)(t * B_ + m)) * HID_ + u0 + ul] = hh;
        }

        // ---- grid barrier (skip after last step) ----
        if (t < T_ - 1) {
            __syncthreads();
            if (tid == 0) {
                __threadfence();
                atomicAdd(bar, 1u);
                unsigned target = (unsigned)(t + 1) * NBLK;
                while (ld_acq(bar) < target) { }
            }
            __syncthreads();
        }
    }
}

// ---------------- launch ----------------------------------------------------
extern "C" void kernel_launch(void* const* d_in, const int* in_sizes, int n_in,
                              void* d_out, int out_size) {
    const int*   data = (const int*)d_in[0];
    const float* emb  = (const float*)d_in[2];
    const float* W0   = (const float*)d_in[3];
    const float* b0   = (const float*)d_in[4];
    const float* W1   = (const float*)d_in[5];
    const float* b1   = (const float*)d_in[6];
    const float* W2   = (const float*)d_in[7];
    const float* b2   = (const float*)d_in[8];
    const float* Wd   = (const float*)d_in[9];
    const float* bd   = (const float*)d_in[10];
    float* out = (float*)d_out;
    (void)in_sizes; (void)n_in; (void)out_size;

    float *X0, *HA, *HB, *Xg, *h;
    unsigned* bar;
    cudaGetSymbolAddress((void**)&X0, g_X0);
    cudaGetSymbolAddress((void**)&HA, g_HA);
    cudaGetSymbolAddress((void**)&HB, g_HB);
    cudaGetSymbolAddress((void**)&Xg, g_Xg);
    cudaGetSymbolAddress((void**)&h,  g_h);
    cudaGetSymbolAddress((void**)&bar, g_bar);

    cudaFuncSetAttribute(lstm_persist, cudaFuncAttributeMaxDynamicSharedMemorySize,
                         SMEM_PERSIST);

    gather_kernel<<<TB_, 128>>>(data, emb, X0);

    const int zgrid = (2 * BH + 255) / 256;

    // layer 0
    zero_state<<<zgrid, 256>>>(h, bar);
    gemm_tf32_bias<<<dim3(G_ / 128, TB_ / 128), 256>>>(X0, EMB_, W0, G_, b0, Xg, G_, EMB_);
    lstm_persist<<<NBLK, 128, SMEM_PERSIST>>>(Xg, W0 + (size_t)EMB_ * G_, h, HA, bar);

    // layer 1
    zero_state<<<zgrid, 256>>>(h, bar);
    gemm_tf32_bias<<<dim3(G_ / 128, TB_ / 128), 256>>>(HA, HID_, W1, G_, b1, Xg, G_, HID_);
    lstm_persist<<<NBLK, 128, SMEM_PERSIST>>>(Xg, W1 + (size_t)HID_ * G_, h, HB, bar);

    // layer 2
    zero_state<<<zgrid, 256>>>(h, bar);
    gemm_tf32_bias<<<dim3(G_ / 128, TB_ / 128), 256>>>(HB, HID_, W2, G_, b2, Xg, G_, HID_);
    lstm_persist<<<NBLK, 128, SMEM_PERSIST>>>(Xg, W2 + (size_t)HID_ * G_, h, HA, bar);

    // projection
    gemm_tf32_bias<<<dim3(VOCAB_ / 128, TB_ / 128), 256>>>(HA, HID_, Wd, VOCAB_, bd,
                                                           out, VOCAB_, HID_);
}

// round 3
// speedup vs baseline: 2.2322x; 1.0945x over previous
#include <cuda_runtime.h>
#include <cstdint>
#include <math.h>

#define T_     256
#define B_     32
#define VOCAB_ 32000
#define EMB_   512
#define HID_   1024
#define G_     4096   // 4*HID
#define TB_    8192   // T_*B_
#define NBLK   128    // persistent blocks (1 per SM)
#define UPB    8      // hidden units per block (128*8 = 1024)
#define BH     (B_ * HID_)
#define NW     8      // warps per block in lstm_persist

// ---------------- scratch (device globals; no allocations allowed) ----------
__device__ float g_X0[TB_ * EMB_];
__device__ float g_HA[TB_ * HID_];
__device__ float g_HB[TB_ * HID_];
__device__ float g_Xg[(size_t)TB_ * G_];
__device__ float g_h[2 * BH];              // ping-pong h state
__device__ unsigned g_bar;                 // grid barrier counter

// ---------------- helpers ---------------------------------------------------
__device__ __forceinline__ float f2tf32(float x) {
    uint32_t u;
    asm("cvt.rna.tf32.f32 %0, %1;" : "=r"(u) : "f"(x));
    return __uint_as_float(u);
}

__device__ __forceinline__ void mma_tf32(float* d, const uint32_t* a, const uint32_t* b) {
    asm volatile(
        "mma.sync.aligned.m16n8k8.row.col.f32.tf32.tf32.f32 "
        "{%0,%1,%2,%3}, {%4,%5,%6,%7}, {%8,%9}, {%0,%1,%2,%3};\n"
        : "+f"(d[0]), "+f"(d[1]), "+f"(d[2]), "+f"(d[3])
        : "r"(a[0]), "r"(a[1]), "r"(a[2]), "r"(a[3]), "r"(b[0]), "r"(b[1]));
}

__device__ __forceinline__ float sigm(float x) { return 1.f / (1.f + expf(-x)); }

__device__ __forceinline__ unsigned ld_acq(const unsigned* p) {
    unsigned v;
    asm volatile("ld.acquire.gpu.u32 %0, [%1];" : "=r"(v) : "l"(p) : "memory");
    return v;
}

// Hs swizzle: addr(k, m) = k*32 + (m ^ fsw(k));  STS <=2-way, LDS conflict-free
__device__ __forceinline__ int fsw(int k) {
    return ((k & 3) << 3) ^ (((k >> 2) & 7) << 2);
}

// ---------------- embedding gather ------------------------------------------
__global__ void gather_kernel(const int* __restrict__ data,
                              const float* __restrict__ emb,
                              float* __restrict__ X0) {
    int tb = blockIdx.x;
    int idx = data[tb];
    const float4* src = reinterpret_cast<const float4*>(emb + (size_t)idx * EMB_);
    float4* dst = reinterpret_cast<float4*>(X0 + (size_t)tb * EMB_);
    dst[threadIdx.x] = src[threadIdx.x];
}

// ---------------- state zero + barrier reset --------------------------------
__global__ void zero_state(float* __restrict__ h, unsigned* __restrict__ bar) {
    int i = blockIdx.x * blockDim.x + threadIdx.x;
    if (i < 2 * BH) h[i] = 0.f;
    if (i == 0) *bar = 0u;
}

// ---------------- generic TF32 GEMM: C = A@B + bias (validated) -------------
__global__ __launch_bounds__(256) void gemm_tf32_bias(
    const float* __restrict__ A, int lda,
    const float* __restrict__ Bm, int ldb,
    const float* __restrict__ bias,
    float* __restrict__ C, int ldc, int K)
{
    __shared__ float As[16][132];
    __shared__ float Bs[16][136];

    const int n0 = blockIdx.x * 128;
    const int m0 = blockIdx.y * 128;
    const int tid = threadIdx.x;
    const int lane = tid & 31, warp = tid >> 5;
    const int wm = (warp & 3) * 32;
    const int wn = (warp >> 2) * 64;
    const int g = lane >> 2, tig = lane & 3;

    float acc[2][8][4];
#pragma unroll
    for (int i = 0; i < 2; i++)
#pragma unroll
        for (int j = 0; j < 8; j++)
#pragma unroll
            for (int r = 0; r < 4; r++) acc[i][j][r] = 0.f;

    float4 ra[2], rb[2];

    auto ldglobal = [&](int k0) {
#pragma unroll
        for (int i = 0; i < 2; i++) {
            int c = tid + i * 256;
            int r = c >> 2, kq = (c & 3) << 2;
            ra[i] = *reinterpret_cast<const float4*>(A + (size_t)(m0 + r) * lda + (k0 + kq));
            int k = c >> 5, nq = (c & 31) << 2;
            rb[i] = *reinterpret_cast<const float4*>(Bm + (size_t)(k0 + k) * ldb + (n0 + nq));
        }
    };
    auto st_smem = [&]() {
#pragma unroll
        for (int i = 0; i < 2; i++) {
            int c = tid + i * 256;
            int r = c >> 2, kq = (c & 3) << 2;
            As[kq + 0][r] = f2tf32(ra[i].x);
            As[kq + 1][r] = f2tf32(ra[i].y);
            As[kq + 2][r] = f2tf32(ra[i].z);
            As[kq + 3][r] = f2tf32(ra[i].w);
            int k = c >> 5, nq = (c & 31) << 2;
            float4 t;
            t.x = f2tf32(rb[i].x); t.y = f2tf32(rb[i].y);
            t.z = f2tf32(rb[i].z); t.w = f2tf32(rb[i].w);
            *reinterpret_cast<float4*>(&Bs[k][nq]) = t;
        }
    };
    auto compute = [&]() {
#pragma unroll
        for (int ks = 0; ks < 16; ks += 8) {
            uint32_t af[2][4];
#pragma unroll
            for (int mt = 0; mt < 2; mt++) {
                int mb = wm + mt * 16;
                af[mt][0] = __float_as_uint(As[ks + tig][mb + g]);
                af[mt][1] = __float_as_uint(As[ks + tig][mb + g + 8]);
                af[mt][2] = __float_as_uint(As[ks + tig + 4][mb + g]);
                af[mt][3] = __float_as_uint(As[ks + tig + 4][mb + g + 8]);
            }
#pragma unroll
            for (int nt = 0; nt < 8; nt++) {
                uint32_t bf[2];
                int nb = wn + nt * 8;
                bf[0] = __float_as_uint(Bs[ks + tig][nb + g]);
                bf[1] = __float_as_uint(Bs[ks + tig + 4][nb + g]);
                mma_tf32(acc[0][nt], af[0], bf);
                mma_tf32(acc[1][nt], af[1], bf);
            }
        }
    };

    ldglobal(0); st_smem(); __syncthreads();
    const int nk = K >> 4;
    for (int kb = 0; kb < nk; kb++) {
        bool more = (kb + 1 < nk);
        if (more) ldglobal((kb + 1) << 4);
        compute();
        __syncthreads();
        if (more) { st_smem(); __syncthreads(); }
    }

#pragma unroll
    for (int mt = 0; mt < 2; mt++) {
        int m = m0 + wm + mt * 16 + g;
#pragma unroll
        for (int nt = 0; nt < 8; nt++) {
            int n = n0 + wn + nt * 8 + 2 * tig;
            float bx = bias[n], by = bias[n + 1];
            float2 v0 = make_float2(acc[mt][nt][0] + bx, acc[mt][nt][1] + by);
            float2 v1 = make_float2(acc[mt][nt][2] + bx, acc[mt][nt][3] + by);
            *reinterpret_cast<float2*>(C + (size_t)m * ldc + n) = v0;
            *reinterpret_cast<float2*>(C + (size_t)(m + 8) * ldc + n) = v1;
        }
    }
}

// ---------------- persistent LSTM layer -------------------------------------
// 128 blocks x 256 threads (8 warps). Block owns UPB=8 units (32 gate cols).
// Wh slice resident in SMEM as mma B-fragments for all 256 steps.
// K split 8 ways across warps (128 K each, 2 chunks of 64).
// c state in registers; Xg prefetched across the grid barrier.
//
// Dynamic SMEM:
//   Whs : float2[128 ko][4 nt][32 lane]              = 131072 B
//   Hs  : float [8 warp][64 k][32 m] (swizzled)      =  65536 B
//   scr : aliases Hs (32 KB needed, Hs dead by then)
#define WHS_BYTES 131072
#define HS_BYTES  65536
#define SMEM_PERSIST (WHS_BYTES + HS_BYTES)

__global__ __launch_bounds__(256, 1) void lstm_persist(
    const float* __restrict__ Xg,
    const float* __restrict__ Wh,      // [HID_][G_] (rows Din..Din+H of W)
    float* __restrict__ hbuf,          // [2][BH] (zeroed)
    float* __restrict__ Hout,          // [TB_][HID_]
    unsigned* __restrict__ bar)
{
    extern __shared__ char smx[];
    float2* Whs = reinterpret_cast<float2*>(smx);
    float*  Hs  = reinterpret_cast<float*>(smx + WHS_BYTES);
    float*  scr = Hs;                  // alias: used only after compute done

    const int tid = threadIdx.x;
    const int lane = tid & 31, warp = tid >> 5;
    const int g = lane >> 2, tig = lane & 3;
    const int u0 = blockIdx.x * UPB;
    float* Hw = Hs + warp * 2048;      // this warp's 64k x 32m chunk buffer

    // ---- one-time: load Wh slice into fragment layout ----
    for (int ko = warp; ko < 128; ko += NW) {
#pragma unroll
        for (int nt = 0; nt < 4; nt++) {
            int col = nt * HID_ + u0 + g;
            float b0 = Wh[(size_t)(ko * 8 + tig) * G_ + col];
            float b1 = Wh[(size_t)(ko * 8 + tig + 4) * G_ + col];
            Whs[(ko * 4 + nt) * 32 + lane] = make_float2(f2tf32(b0), f2tf32(b1));
        }
    }
    __syncthreads();

    // pointwise mapping for this thread: p = tid -> (batch m, unit ul)
    const int pm = tid >> 3, pul = tid & 7;
    const int pmt = pm >> 4;
    const int pgg = (pm & 15) & 7, phi = (pm & 15) >> 3;
    const int pr = phi * 2 + (pul & 1);
    const int pln = pgg * 4 + (pul >> 1);
    const size_t xgbase = (size_t)pm * G_ + u0 + pul;

    float creg = 0.f;
    float xr[4];
#pragma unroll
    for (int s = 0; s < 4; s++) xr[s] = Xg[xgbase + s * HID_];   // t = 0 prefetch

    for (int t = 0; t < T_; t++) {
        const float* hin = hbuf + (t & 1) * BH;
        float* hnx = hbuf + ((t + 1) & 1) * BH;

        float acc[2][4][4];
#pragma unroll
        for (int mt = 0; mt < 2; mt++)
#pragma unroll
            for (int nt = 0; nt < 4; nt++)
#pragma unroll
                for (int r = 0; r < 4; r++) acc[mt][nt][r] = 0.f;

        float4 rr[16];
        const int kw = warp * 128;     // this warp's K base (128 wide)

        auto ldg_chunk = [&](int c) {
            int kb = kw + c * 64;
#pragma unroll
            for (int i = 0; i < 16; i++) {
                int idx = i * 32 + lane;
                int row = idx >> 4, kq = (idx & 15) << 2;
                rr[i] = *reinterpret_cast<const float4*>(hin + row * HID_ + kb + kq);
            }
        };
        auto sts_chunk = [&]() {
#pragma unroll
            for (int i = 0; i < 16; i++) {
                int idx = i * 32 + lane;
                int row = idx >> 4, kq = (idx & 15) << 2;
                float v[4] = {rr[i].x, rr[i].y, rr[i].z, rr[i].w};
#pragma unroll
                for (int j = 0; j < 4; j++) {
                    int k = kq + j;
                    Hw[(k << 5) + (row ^ fsw(k))] = f2tf32(v[j]);
                }
            }
        };
        auto compute_chunk = [&](int c) {
#pragma unroll
            for (int ks8 = 0; ks8 < 8; ks8++) {
                int ko = warp * 16 + c * 8 + ks8;   // global k/8 index
                uint32_t af[2][4];
#pragma unroll
                for (int mt = 0; mt < 2; mt++) {
                    int mb = mt * 16;
                    int kA = ks8 * 8 + tig;
                    int kB = kA + 4;
                    af[mt][0] = __float_as_uint(Hw[(kA << 5) + ((mb + g) ^ fsw(kA))]);
                    af[mt][1] = __float_as_uint(Hw[(kA << 5) + ((mb + g + 8) ^ fsw(kA))]);
                    af[mt][2] = __float_as_uint(Hw[(kB << 5) + ((mb + g) ^ fsw(kB))]);
                    af[mt][3] = __float_as_uint(Hw[(kB << 5) + ((mb + g + 8) ^ fsw(kB))]);
                }
#pragma unroll
                for (int nt = 0; nt < 4; nt++) {
                    float2 bb = Whs[(ko * 4 + nt) * 32 + lane];
                    uint32_t bf[2] = {__float_as_uint(bb.x), __float_as_uint(bb.y)};
                    mma_tf32(acc[0][nt], af[0], bf);
                    mma_tf32(acc[1][nt], af[1], bf);
                }
            }
        };

        ldg_chunk(0);
        sts_chunk();
        __syncwarp();
        ldg_chunk(1);
        compute_chunk(0);
        __syncwarp();
        sts_chunk();
        __syncwarp();
        compute_chunk(1);

        // ---- reduce K-partials across 8 warps (scr aliases Hs) ----
        __syncthreads();
#pragma unroll
        for (int mt = 0; mt < 2; mt++)
#pragma unroll
            for (int nt = 0; nt < 4; nt++)
#pragma unroll
                for (int r = 0; r < 4; r++) {
                    int ridx = mt * 16 + nt * 4 + r;
                    scr[((warp * 32 + ridx) << 5) + lane] = acc[mt][nt][r];
                }
        __syncthreads();

        // ---- pointwise: one (batch, unit) pair per thread ----
        {
            float gv[4];
#pragma unroll
            for (int s = 0; s < 4; s++) {
                int ridx = pmt * 16 + s * 4 + pr;
                float v = 0.f;
#pragma unroll
                for (int w = 0; w < NW; w++)
                    v += scr[((w * 32 + ridx) << 5) + pln];
                gv[s] = v + xr[s];
            }
            float cc = creg;
            cc = sigm(gv[2] + 1.f) * cc + sigm(gv[0]) * tanhf(gv[1]);
            float hh = sigm(gv[3]) * tanhf(cc);
            creg = cc;
            hnx[pm * HID_ + u0 + pul] = hh;
            Hout[((size_t)(t * B_ + pm)) * HID_ + u0 + pul] = hh;
        }

        // ---- grid barrier with Xg prefetch overlap (skip after last) ----
        if (t < T_ - 1) {
            __syncthreads();           // all hnx stores issued
            if (tid == 0) {
                __threadfence();
                atomicAdd(bar, 1u);
            }
            // prefetch Xg for step t+1 while the barrier settles
            const size_t xb = xgbase + (size_t)(t + 1) * B_ * G_;
#pragma unroll
            for (int s = 0; s < 4; s++) xr[s] = Xg[xb + s * HID_];
            if (tid == 0) {
                unsigned target = (unsigned)(t + 1) * NBLK;
                while (ld_acq(bar) < target) { }
            }
            __syncthreads();
        }
    }
}

// ---------------- launch ----------------------------------------------------
extern "C" void kernel_launch(void* const* d_in, const int* in_sizes, int n_in,
                              void* d_out, int out_size) {
    const int*   data = (const int*)d_in[0];
    const float* emb  = (const float*)d_in[2];
    const float* W0   = (const float*)d_in[3];
    const float* b0   = (const float*)d_in[4];
    const float* W1   = (const float*)d_in[5];
    const float* b1   = (const float*)d_in[6];
    const float* W2   = (const float*)d_in[7];
    const float* b2   = (const float*)d_in[8];
    const float* Wd   = (const float*)d_in[9];
    const float* bd   = (const float*)d_in[10];
    float* out = (float*)d_out;
    (void)in_sizes; (void)n_in; (void)out_size;

    float *X0, *HA, *HB, *Xg, *h;
    unsigned* bar;
    cudaGetSymbolAddress((void**)&X0, g_X0);
    cudaGetSymbolAddress((void**)&HA, g_HA);
    cudaGetSymbolAddress((void**)&HB, g_HB);
    cudaGetSymbolAddress((void**)&Xg, g_Xg);
    cudaGetSymbolAddress((void**)&h,  g_h);
    cudaGetSymbolAddress((void**)&bar, g_bar);

    cudaFuncSetAttribute(lstm_persist, cudaFuncAttributeMaxDynamicSharedMemorySize,
                         SMEM_PERSIST);

    gather_kernel<<<TB_, 128>>>(data, emb, X0);

    const int zgrid = (2 * BH + 255) / 256;

    // layer 0
    zero_state<<<zgrid, 256>>>(h, bar);
    gemm_tf32_bias<<<dim3(G_ / 128, TB_ / 128), 256>>>(X0, EMB_, W0, G_, b0, Xg, G_, EMB_);
    lstm_persist<<<NBLK, 256, SMEM_PERSIST>>>(Xg, W0 + (size_t)EMB_ * G_, h, HA, bar);

    // layer 1
    zero_state<<<zgrid, 256>>>(h, bar);
    gemm_tf32_bias<<<dim3(G_ / 128, TB_ / 128), 256>>>(HA, HID_, W1, G_, b1, Xg, G_, HID_);
    lstm_persist<<<NBLK, 256, SMEM_PERSIST>>>(Xg, W1 + (size_t)HID_ * G_, h, HB, bar);

    // layer 2
    zero_state<<<zgrid, 256>>>(h, bar);
    gemm_tf32_bias<<<dim3(G_ / 128, TB_ / 128), 256>>>(HB, HID_, W2, G_, b2, Xg, G_, HID_);
    lstm_persist<<<NBLK, 256, SMEM_PERSIST>>>(Xg, W2 + (size_t)HID_ * G_, h, HA, bar);

    // projection
    gemm_tf32_bias<<<dim3(VOCAB_ / 128, TB_ / 128), 256>>>(HA, HID_, Wd, VOCAB_, bd,
                                                           out, VOCAB_, HID_);
}

// round 4
// speedup vs baseline: 2.2657x; 1.0150x over previous
#include <cuda_runtime.h>
#include <cstdint>
#include <math.h>

#define T_     256
#define B_     32
#define VOCAB_ 32000
#define EMB_   512
#define HID_   1024
#define G_     4096   // 4*HID
#define TB_    8192   // T_*B_
#define NBLK   128    // persistent blocks (1 per SM)
#define UPB    8      // hidden units per block (128*8 = 1024)
#define BH     (B_ * HID_)
#define NW     8      // warps per block in lstm_persist

// chunking for the recurrence h staging
#define CHK    32                   // K per chunk
#define CSTRIDE 36                  // floats per row in chunk buf (pad 4)
#define CBYTES (32 * CSTRIDE * 4)   // 4608 B per chunk buffer

// ---------------- scratch (device globals; no allocations allowed) ----------
__device__ float g_X0[TB_ * EMB_];
__device__ float g_HA[TB_ * HID_];
__device__ float g_HB[TB_ * HID_];
__device__ float g_Xg[(size_t)TB_ * G_];
__device__ float g_h[2 * BH];              // ping-pong h state
__device__ unsigned g_bar;                 // grid barrier counter

// ---------------- helpers ---------------------------------------------------
__device__ __forceinline__ float f2tf32(float x) {
    uint32_t u;
    asm("cvt.rna.tf32.f32 %0, %1;" : "=r"(u) : "f"(x));
    return __uint_as_float(u);
}

__device__ __forceinline__ void mma_tf32(float* d, const uint32_t* a, const uint32_t* b) {
    asm volatile(
        "mma.sync.aligned.m16n8k8.row.col.f32.tf32.tf32.f32 "
        "{%0,%1,%2,%3}, {%4,%5,%6,%7}, {%8,%9}, {%0,%1,%2,%3};\n"
        : "+f"(d[0]), "+f"(d[1]), "+f"(d[2]), "+f"(d[3])
        : "r"(a[0]), "r"(a[1]), "r"(a[2]), "r"(a[3]), "r"(b[0]), "r"(b[1]));
}

__device__ __forceinline__ float sigm(float x) { return 1.f / (1.f + expf(-x)); }

__device__ __forceinline__ unsigned ld_acq(const unsigned* p) {
    unsigned v;
    asm volatile("ld.acquire.gpu.u32 %0, [%1];" : "=r"(v) : "l"(p) : "memory");
    return v;
}

__device__ __forceinline__ void cp16(uint32_t dst, const void* src) {
    asm volatile("cp.async.cg.shared.global [%0], [%1], 16;" :: "r"(dst), "l"(src));
}
#define CP_COMMIT() asm volatile("cp.async.commit_group;")
#define CP_WAIT(N)  asm volatile("cp.async.wait_group %0;" :: "n"(N))

// ---------------- embedding gather ------------------------------------------
__global__ void gather_kernel(const int* __restrict__ data,
                              const float* __restrict__ emb,
                              float* __restrict__ X0) {
    int tb = blockIdx.x;
    int idx = data[tb];
    const float4* src = reinterpret_cast<const float4*>(emb + (size_t)idx * EMB_);
    float4* dst = reinterpret_cast<float4*>(X0 + (size_t)tb * EMB_);
    dst[threadIdx.x] = src[threadIdx.x];
}

// ---------------- state zero + barrier reset --------------------------------
__global__ void zero_state(float* __restrict__ h, unsigned* __restrict__ bar) {
    int i = blockIdx.x * blockDim.x + threadIdx.x;
    if (i < 2 * BH) h[i] = 0.f;
    if (i == 0) *bar = 0u;
}

// ---------------- generic TF32 GEMM: C = A@B + bias (validated) -------------
__global__ __launch_bounds__(256) void gemm_tf32_bias(
    const float* __restrict__ A, int lda,
    const float* __restrict__ Bm, int ldb,
    const float* __restrict__ bias,
    float* __restrict__ C, int ldc, int K)
{
    __shared__ float As[16][132];
    __shared__ float Bs[16][136];

    const int n0 = blockIdx.x * 128;
    const int m0 = blockIdx.y * 128;
    const int tid = threadIdx.x;
    const int lane = tid & 31, warp = tid >> 5;
    const int wm = (warp & 3) * 32;
    const int wn = (warp >> 2) * 64;
    const int g = lane >> 2, tig = lane & 3;

    float acc[2][8][4];
#pragma unroll
    for (int i = 0; i < 2; i++)
#pragma unroll
        for (int j = 0; j < 8; j++)
#pragma unroll
            for (int r = 0; r < 4; r++) acc[i][j][r] = 0.f;

    float4 ra[2], rb[2];

    auto ldglobal = [&](int k0) {
#pragma unroll
        for (int i = 0; i < 2; i++) {
            int c = tid + i * 256;
            int r = c >> 2, kq = (c & 3) << 2;
            ra[i] = *reinterpret_cast<const float4*>(A + (size_t)(m0 + r) * lda + (k0 + kq));
            int k = c >> 5, nq = (c & 31) << 2;
            rb[i] = *reinterpret_cast<const float4*>(Bm + (size_t)(k0 + k) * ldb + (n0 + nq));
        }
    };
    auto st_smem = [&]() {
#pragma unroll
        for (int i = 0; i < 2; i++) {
            int c = tid + i * 256;
            int r = c >> 2, kq = (c & 3) << 2;
            As[kq + 0][r] = f2tf32(ra[i].x);
            As[kq + 1][r] = f2tf32(ra[i].y);
            As[kq + 2][r] = f2tf32(ra[i].z);
            As[kq + 3][r] = f2tf32(ra[i].w);
            int k = c >> 5, nq = (c & 31) << 2;
            float4 t;
            t.x = f2tf32(rb[i].x); t.y = f2tf32(rb[i].y);
            t.z = f2tf32(rb[i].z); t.w = f2tf32(rb[i].w);
            *reinterpret_cast<float4*>(&Bs[k][nq]) = t;
        }
    };
    auto compute = [&]() {
#pragma unroll
        for (int ks = 0; ks < 16; ks += 8) {
            uint32_t af[2][4];
#pragma unroll
            for (int mt = 0; mt < 2; mt++) {
                int mb = wm + mt * 16;
                af[mt][0] = __float_as_uint(As[ks + tig][mb + g]);
                af[mt][1] = __float_as_uint(As[ks + tig][mb + g + 8]);
                af[mt][2] = __float_as_uint(As[ks + tig + 4][mb + g]);
                af[mt][3] = __float_as_uint(As[ks + tig + 4][mb + g + 8]);
            }
#pragma unroll
            for (int nt = 0; nt < 8; nt++) {
                uint32_t bf[2];
                int nb = wn + nt * 8;
                bf[0] = __float_as_uint(Bs[ks + tig][nb + g]);
                bf[1] = __float_as_uint(Bs[ks + tig + 4][nb + g]);
                mma_tf32(acc[0][nt], af[0], bf);
                mma_tf32(acc[1][nt], af[1], bf);
            }
        }
    };

    ldglobal(0); st_smem(); __syncthreads();
    const int nk = K >> 4;
    for (int kb = 0; kb < nk; kb++) {
        bool more = (kb + 1 < nk);
        if (more) ldglobal((kb + 1) << 4);
        compute();
        __syncthreads();
        if (more) { st_smem(); __syncthreads(); }
    }

#pragma unroll
    for (int mt = 0; mt < 2; mt++) {
        int m = m0 + wm + mt * 16 + g;
#pragma unroll
        for (int nt = 0; nt < 8; nt++) {
            int n = n0 + wn + nt * 8 + 2 * tig;
            float bx = bias[n], by = bias[n + 1];
            float2 v0 = make_float2(acc[mt][nt][0] + bx, acc[mt][nt][1] + by);
            float2 v1 = make_float2(acc[mt][nt][2] + bx, acc[mt][nt][3] + by);
            *reinterpret_cast<float2*>(C + (size_t)m * ldc + n) = v0;
            *reinterpret_cast<float2*>(C + (size_t)(m + 8) * ldc + n) = v1;
        }
    }
}

// ---------------- persistent LSTM layer -------------------------------------
// 128 blocks x 256 threads (8 warps). Block owns UPB=8 units (32 gate cols).
// Wh slice resident in SMEM as mma B-fragments for all 256 steps.
// K split 8 ways across warps (128 K each, 4 cp.async chunks of 32, 2 bufs).
// c state in registers; Xg prefetched and Hout stored across the barrier.
//
// Dynamic SMEM:
//   Whs : float2[128 ko][4 nt][32 lane]              = 131072 B
//   Hb  : per-warp 2 x [32 m][36] chunk buffers      =  73728 B
//   scr : aliases Hb (32 KB needed; Hb drained first)
#define WHS_BYTES 131072
#define HB_BYTES  (NW * 2 * CBYTES)
#define SMEM_PERSIST (WHS_BYTES + HB_BYTES)

__global__ __launch_bounds__(256, 1) void lstm_persist(
    const float* __restrict__ Xg,
    const float* __restrict__ Wh,      // [HID_][G_] (rows Din..Din+H of W)
    float* __restrict__ hbuf,          // [2][BH] (zeroed; tf32-rounded values)
    float* __restrict__ Hout,          // [TB_][HID_]
    unsigned* __restrict__ bar)
{
    extern __shared__ char smx[];
    float2* Whs = reinterpret_cast<float2*>(smx);
    float*  scr = reinterpret_cast<float*>(smx + WHS_BYTES);   // alias of Hb

    const int tid = threadIdx.x;
    const int lane = tid & 31, warp = tid >> 5;
    const int g = lane >> 2, tig = lane & 3;
    const int u0 = blockIdx.x * UPB;

    const uint32_t smem_u32 = (uint32_t)__cvta_generic_to_shared(smx);
    const uint32_t hb_u32 = smem_u32 + WHS_BYTES + warp * 2 * CBYTES;
    float* hb_gen = reinterpret_cast<float*>(smx + WHS_BYTES + warp * 2 * CBYTES);

    // ---- one-time: load Wh slice into fragment layout ----
    for (int ko = warp; ko < 128; ko += NW) {
#pragma unroll
        for (int nt = 0; nt < 4; nt++) {
            int col = nt * HID_ + u0 + g;
            float b0 = Wh[(size_t)(ko * 8 + tig) * G_ + col];
            float b1 = Wh[(size_t)(ko * 8 + tig + 4) * G_ + col];
            Whs[(ko * 4 + nt) * 32 + lane] = make_float2(f2tf32(b0), f2tf32(b1));
        }
    }
    __syncthreads();

    // pointwise mapping for this thread: p = tid -> (batch m, unit ul)
    const int pm = tid >> 3, pul = tid & 7;
    const int pmt = pm >> 4;
    const int pgg = (pm & 15) & 7, phi = (pm & 15) >> 3;
    const int pr = phi * 2 + (pul & 1);
    const int pln = pgg * 4 + (pul >> 1);
    const size_t xgbase = (size_t)pm * G_ + u0 + pul;

    // cp.async addressing for this thread
    const int r8 = lane >> 3, kk = lane & 7;
    const int kw = warp * 128;         // this warp's K base

    float creg = 0.f;
    float xr[4];
#pragma unroll
    for (int s = 0; s < 4; s++) xr[s] = Xg[xgbase + s * HID_];   // t = 0 prefetch

    for (int t = 0; t < T_; t++) {
        const float* hin = hbuf + (t & 1) * BH;
        float* hnx = hbuf + ((t + 1) & 1) * BH;

        float acc[2][4][4];
#pragma unroll
        for (int mt = 0; mt < 2; mt++)
#pragma unroll
            for (int nt = 0; nt < 4; nt++)
#pragma unroll
                for (int r = 0; r < 4; r++) acc[mt][nt][r] = 0.f;

        auto cp_chunk = [&](int c, int b) {
            const int kbase = kw + c * CHK;
            const uint32_t dbase = hb_u32 + b * CBYTES + (kk * 4) * 4;
            const float* sbase = hin + r8 * HID_ + kbase + kk * 4;
#pragma unroll
            for (int p = 0; p < 8; p++) {
                int row4 = p * 4;      // + r8 handled in bases
                cp16(dbase + (uint32_t)((row4 + r8) * CSTRIDE) * 4,
                     sbase + (size_t)row4 * HID_);
            }
            CP_COMMIT();
        };
        auto compute_chunk = [&](int c, int b) {
            const float* buf = hb_gen + b * (CBYTES / 4);
#pragma unroll
            for (int k8 = 0; k8 < 4; k8++) {
                int ko = warp * 16 + c * 4 + k8;
                int kA = k8 * 8 + tig;
                uint32_t af[2][4];
#pragma unroll
                for (int mt = 0; mt < 2; mt++) {
                    int mb = mt * 16;
                    af[mt][0] = __float_as_uint(buf[(mb + g) * CSTRIDE + kA]);
                    af[mt][1] = __float_as_uint(buf[(mb + g + 8) * CSTRIDE + kA]);
                    af[mt][2] = __float_as_uint(buf[(mb + g) * CSTRIDE + kA + 4]);
                    af[mt][3] = __float_as_uint(buf[(mb + g + 8) * CSTRIDE + kA + 4]);
                }
#pragma unroll
                for (int nt = 0; nt < 4; nt++) {
                    float2 bb = Whs[(ko * 4 + nt) * 32 + lane];
                    uint32_t bf[2] = {__float_as_uint(bb.x), __float_as_uint(bb.y)};
                    mma_tf32(acc[0][nt], af[0], bf);
                    mma_tf32(acc[1][nt], af[1], bf);
                }
            }
        };

        // 2-deep cp.async pipeline over 4 chunks
        cp_chunk(0, 0);
        cp_chunk(1, 1);
        CP_WAIT(1); __syncwarp();
        compute_chunk(0, 0);
        cp_chunk(2, 0);
        CP_WAIT(1); __syncwarp();
        compute_chunk(1, 1);
        cp_chunk(3, 1);
        CP_WAIT(1); __syncwarp();
        compute_chunk(2, 0);
        CP_WAIT(0); __syncwarp();
        compute_chunk(3, 1);

        // ---- reduce K-partials across 8 warps (scr aliases chunk bufs) ----
        __syncthreads();
#pragma unroll
        for (int mt = 0; mt < 2; mt++)
#pragma unroll
            for (int nt = 0; nt < 4; nt++)
#pragma unroll
                for (int r = 0; r < 4; r++) {
                    int ridx = mt * 16 + nt * 4 + r;
                    scr[((warp * 32 + ridx) << 5) + lane] = acc[mt][nt][r];
                }
        __syncthreads();

        // ---- pointwise: one (batch, unit) pair per thread ----
        float hh;
        {
            float gv[4];
#pragma unroll
            for (int s = 0; s < 4; s++) {
                int ridx = pmt * 16 + s * 4 + pr;
                float v = 0.f;
#pragma unroll
                for (int w = 0; w < NW; w++)
                    v += scr[((w * 32 + ridx) << 5) + pln];
                gv[s] = v + xr[s];
            }
            float cc = creg;
            cc = sigm(gv[2] + 1.f) * cc + sigm(gv[0]) * tanhf(gv[1]);
            hh = sigm(gv[3]) * tanhf(cc);
            creg = cc;
            hnx[pm * HID_ + u0 + pul] = f2tf32(hh);   // rounded once for next-step mma
        }

        // ---- grid barrier; Hout store + Xg prefetch overlap the wait ----
        if (t < T_ - 1) {
            __syncthreads();           // all hnx stores issued
            if (tid == 0) {
                __threadfence();
                atomicAdd(bar, 1u);
            }
            Hout[((size_t)(t * B_ + pm)) * HID_ + u0 + pul] = hh;
            const size_t xb = xgbase + (size_t)(t + 1) * B_ * G_;
#pragma unroll
            for (int s = 0; s < 4; s++) xr[s] = Xg[xb + s * HID_];
            if (tid == 0) {
                unsigned target = (unsigned)(t + 1) * NBLK;
                while (ld_acq(bar) < target) { }
            }
            __syncthreads();
        } else {
            Hout[((size_t)(t * B_ + pm)) * HID_ + u0 + pul] = hh;
        }
    }
}

// ---------------- launch ----------------------------------------------------
extern "C" void kernel_launch(void* const* d_in, const int* in_sizes, int n_in,
                              void* d_out, int out_size) {
    const int*   data = (const int*)d_in[0];
    const float* emb  = (const float*)d_in[2];
    const float* W0   = (const float*)d_in[3];
    const float* b0   = (const float*)d_in[4];
    const float* W1   = (const float*)d_in[5];
    const float* b1   = (const float*)d_in[6];
    const float* W2   = (const float*)d_in[7];
    const float* b2   = (const float*)d_in[8];
    const float* Wd   = (const float*)d_in[9];
    const float* bd   = (const float*)d_in[10];
    float* out = (float*)d_out;
    (void)in_sizes; (void)n_in; (void)out_size;

    float *X0, *HA, *HB, *Xg, *h;
    unsigned* bar;
    cudaGetSymbolAddress((void**)&X0, g_X0);
    cudaGetSymbolAddress((void**)&HA, g_HA);
    cudaGetSymbolAddress((void**)&HB, g_HB);
    cudaGetSymbolAddress((void**)&Xg, g_Xg);
    cudaGetSymbolAddress((void**)&h,  g_h);
    cudaGetSymbolAddress((void**)&bar, g_bar);

    cudaFuncSetAttribute(lstm_persist, cudaFuncAttributeMaxDynamicSharedMemorySize,
                         SMEM_PERSIST);

    gather_kernel<<<TB_, 128>>>(data, emb, X0);

    const int zgrid = (2 * BH + 255) / 256;

    // layer 0
    zero_state<<<zgrid, 256>>>(h, bar);
    gemm_tf32_bias<<<dim3(G_ / 128, TB_ / 128), 256>>>(X0, EMB_, W0, G_, b0, Xg, G_, EMB_);
    lstm_persist<<<NBLK, 256, SMEM_PERSIST>>>(Xg, W0 + (size_t)EMB_ * G_, h, HA, bar);

    // layer 1
    zero_state<<<zgrid, 256>>>(h, bar);
    gemm_tf32_bias<<<dim3(G_ / 128, TB_ / 128), 256>>>(HA, HID_, W1, G_, b1, Xg, G_, HID_);
    lstm_persist<<<NBLK, 256, SMEM_PERSIST>>>(Xg, W1 + (size_t)HID_ * G_, h, HB, bar);

    // layer 2
    zero_state<<<zgrid, 256>>>(h, bar);
    gemm_tf32_bias<<<dim3(G_ / 128, TB_ / 128), 256>>>(HB, HID_, W2, G_, b2, Xg, G_, HID_);
    lstm_persist<<<NBLK, 256, SMEM_PERSIST>>>(Xg, W2 + (size_t)HID_ * G_, h, HA, bar);

    // projection
    gemm_tf32_bias<<<dim3(VOCAB_ / 128, TB_ / 128), 256>>>(HA, HID_, Wd, VOCAB_, bd,
                                                           out, VOCAB_, HID_);
}